// round 7
// baseline (speedup 1.0000x reference)
#include <cuda_runtime.h>
#include <cuda_fp16.h>
#include <cstdint>
#include <math.h>

// Problem dims (fixed by the reference)
#define S_  256
#define B_  256
#define I_  256
#define H_  512
#define G4_ 2048
#define BH_ (B_ * H_)

// ---------------------------------------------------------------------------
// Scratch (device globals; no allocations allowed)
// ---------------------------------------------------------------------------
__device__ __align__(16) __half g_x_h[S_ * B_ * I_];   // x pre-rounded to fp16
__device__ __align__(16) __half g_Wih0[G4_ * I_];
__device__ __align__(16) __half g_Whh0[G4_ * H_];
__device__ __align__(16) __half g_Wih1[G4_ * H_];
__device__ __align__(16) __half g_Whh1[G4_ * H_];
__device__ float g_bias[2][G4_];                       // b_ih + b_hh per layer

__device__ __align__(16) __half g_h0m_h[2][BH_];   // masked h, fp16 mirror (ping-pong)
__device__ __align__(16) __half g_h1m_h[2][BH_];
__device__ __align__(16) float  g_h0m_f32[2][BH_]; // masked h, fp32 (final state out)
__device__ __align__(16) float  g_h1m_f32[2][BH_];
__device__ __align__(16) float  g_c0[2][BH_];
__device__ __align__(16) float  g_c1[2][BH_];
__device__ __align__(16) __half g_h0raw[2][BH_];   // pre-mask layer0 h (fp16), dbl-buffered

// ---------------------------------------------------------------------------
// Helpers
// ---------------------------------------------------------------------------
__device__ __forceinline__ void cpa16(void* sp, const void* gp) {
    unsigned sa = (unsigned)__cvta_generic_to_shared(sp);
    asm volatile("cp.async.cg.shared.global [%0], [%1], 16;\n"
                 :: "r"(sa), "l"(gp) : "memory");
}
__device__ __forceinline__ void cpa_commit() {
    asm volatile("cp.async.commit_group;\n" ::: "memory");
}
__device__ __forceinline__ float sigm_(float x) {
    return 1.0f / (1.0f + __expf(-x));
}
__device__ __forceinline__ float tanh_(float x) {
    float a = fabsf(x);
    float t = __expf(-2.0f * a);
    float r = (1.0f - t) / (1.0f + t);
    return copysignf(r, x);
}
__device__ __forceinline__ void ldsm4(unsigned& r0, unsigned& r1, unsigned& r2,
                                      unsigned& r3, unsigned addr) {
    asm volatile("ldmatrix.sync.aligned.m8n8.x4.shared.b16 {%0,%1,%2,%3}, [%4];"
                 : "=r"(r0), "=r"(r1), "=r"(r2), "=r"(r3) : "r"(addr));
}

// ---------------------------------------------------------------------------
// Prep: ONE fused kernel (keeps launch count low so ncu -s 5 profiles
// lstm_phase).
// ---------------------------------------------------------------------------
__global__ void prep_kernel(const float* __restrict__ x,
                            const float* __restrict__ Wih0, const float* __restrict__ Whh0,
                            const float* __restrict__ Wih1, const float* __restrict__ Whh1,
                            const float* __restrict__ bi0, const float* __restrict__ bh0,
                            const float* __restrict__ bi1, const float* __restrict__ bh1) {
    const int stride = gridDim.x * blockDim.x;
    const int tid0 = blockIdx.x * blockDim.x + threadIdx.x;
    for (int i = tid0; i < S_ * B_ * I_; i += stride) g_x_h[i] = __float2half_rn(x[i]);
    for (int i = tid0; i < G4_ * I_; i += stride) g_Wih0[i] = __float2half_rn(Wih0[i]);
    for (int i = tid0; i < G4_ * H_; i += stride) {
        g_Whh0[i] = __float2half_rn(Whh0[i]);
        g_Wih1[i] = __float2half_rn(Wih1[i]);
        g_Whh1[i] = __float2half_rn(Whh1[i]);
    }
    for (int i = tid0; i < G4_; i += stride) {
        g_bias[0][i] = bi0[i] + bh0[i];
        g_bias[1][i] = bi1[i] + bh1[i];
    }
}

__global__ void init_kernel(const float* __restrict__ h0, const float* __restrict__ c0) {
    int i = blockIdx.x * blockDim.x + threadIdx.x;
    if (i < BH_) {
        float a = h0[i], b = h0[BH_ + i];
        g_h0m_f32[0][i] = a; g_h0m_h[0][i] = __float2half_rn(a);
        g_h1m_f32[0][i] = b; g_h1m_h[0][i] = __float2half_rn(b);
        g_c0[0][i] = c0[i];
        g_c1[0][i] = c0[BH_ + i];
    }
}

__global__ void final_kernel(float* __restrict__ out) {
    int i = blockIdx.x * blockDim.x + threadIdx.x;
    if (i < BH_) {
        size_t base = (size_t)S_ * B_ * H_;
        out[base + i]            = g_h0m_f32[0][i];   // h layer0
        out[base + BH_ + i]      = g_h1m_f32[0][i];   // h layer1
        out[base + 2 * BH_ + i]  = g_c0[0][i];        // c layer0
        out[base + 3 * BH_ + i]  = g_c1[0][i];        // c layer1
    }
}

// ---------------------------------------------------------------------------
// Fused PHASE kernel: phase p runs layer0@t=p (CTAs 0..63) and layer1@t=p-1
// (CTAs 64..127). CTA tile: 64 batch x 32 hidden (128 gate cols).
// 16 warps (512 thr), warp tile 16x32 (wm = m quarter, wg = gate).
// FP16 mma m16n8k16 + ldmatrix.x4; K chunks of 128, 4-stage cp.async ring.
// Rows padded to 136 halfs (272B) -> conflict-free ldmatrix.
// ---------------------------------------------------------------------------
#define KC_    128
#define LDR_   136                         // padded row length in halfs
#define SM_A_H (64 * LDR_)                 // 8704 halfs
#define SM_B_H (128 * LDR_)                // 17408 halfs
#define SM_STG (SM_A_H + SM_B_H)           // 26112 halfs = 52224 B
#define NST_   4
#define SMEM_BYTES (NST_ * SM_STG * 2)     // 208896 B
#define NT_    512

__global__ __launch_bounds__(NT_, 1) void lstm_phase(
    int p,
    const float* __restrict__ done,     // (S, B)
    float* __restrict__ d_out)
{
    extern __shared__ __half sm[];

    const int sub = blockIdx.x >> 6;      // 0: layer0@t=p, 1: layer1@t=p-1
    if (sub == 0 && p == S_) return;
    if (sub == 1 && p == 0)  return;
    const int t  = (sub == 0) ? p : (p - 1);
    const int rp = t & 1, wp = rp ^ 1;

    const __half *A1, *A2, *W1, *W2;
    int nch1, nch2, lda1, lda2, ldw1, ldw2;
    const float* c_in; float* c_out;
    __half* out_raw_h; float* out_raw_f32;
    __half* out_m_h;   float* out_m_f32;

    if (sub == 0) {
        A1 = g_h0m_h[rp];                   lda1 = H_; W1 = g_Whh0; ldw1 = H_; nch1 = H_ / KC_;
        A2 = g_x_h + (size_t)t * B_ * I_;   lda2 = I_; W2 = g_Wih0; ldw2 = I_; nch2 = I_ / KC_;
        c_in = g_c0[rp]; c_out = g_c0[wp];
        out_raw_h = g_h0raw[rp]; out_raw_f32 = nullptr;
        out_m_h = g_h0m_h[wp]; out_m_f32 = g_h0m_f32[wp];
    } else {
        A1 = g_h0raw[rp];                   lda1 = H_; W1 = g_Wih1; ldw1 = H_; nch1 = H_ / KC_;
        A2 = g_h1m_h[rp];                   lda2 = H_; W2 = g_Whh1; ldw2 = H_; nch2 = H_ / KC_;
        c_in = g_c1[rp]; c_out = g_c1[wp];
        out_raw_h = nullptr; out_raw_f32 = d_out + (size_t)t * B_ * H_;
        out_m_h = g_h1m_h[wp]; out_m_f32 = g_h1m_f32[wp];
    }
    const int nch = nch1 + nch2;          // 6 (layer0) or 8 (layer1)

    const int cta = blockIdx.x & 63;
    const int m0  = (cta & 3) * 64;       // batch tile
    const int j0  = (cta >> 2) * 32;      // hidden tile
    const int tid = threadIdx.x;
    const int wid = tid >> 5;
    const int wm  = wid & 3;              // m quarter (16 rows)
    const int wg  = wid >> 2;             // gate (0..3)
    const int lane = tid & 31;
    const int grp = lane >> 2;
    const int tig = lane & 3;

    // ldmatrix per-lane address patterns
    const int mat   = lane >> 3;
    const int mrow  = (mat & 1) * 8 + (lane & 7);   // A: row within 16, col-block (mat>>1)*8
    const int mcol  = (mat >> 1) * 8;
    const int brow  = (mat >> 1) * 8 + (lane & 7);  // B: row within 16, col-block (mat&1)*8
    const int bcol  = (mat & 1) * 8;

    unsigned bufAu[NST_], bufBu[NST_];
    #pragma unroll
    for (int s = 0; s < NST_; s++) {
        bufAu[s] = (unsigned)__cvta_generic_to_shared(sm + s * SM_STG);
        bufBu[s] = bufAu[s] + SM_A_H * 2;
    }

    auto stage = [&](int kc, int buf) {
        const __half* As; const __half* Ws; int kk, la, lw;
        if (kc < nch1) { As = A1; Ws = W1; kk = kc * KC_;          la = lda1; lw = ldw1; }
        else           { As = A2; Ws = W2; kk = (kc - nch1) * KC_; la = lda2; lw = ldw2; }
        __half* sA = sm + buf * SM_STG;
        __half* sB = sA + SM_A_H;
        // A: 64 rows x 128 halfs = 1024 x 16B chunks / 512 thr = 2 each
        #pragma unroll
        for (int i = 0; i < 2; i++) {
            int idx = tid + i * NT_; int m = idx >> 4; int c = (idx & 15) * 8;
            cpa16(&sA[m * LDR_ + c], As + (size_t)(m0 + m) * la + kk + c);
        }
        // B: 128 gate rows x 128 halfs = 2048 chunks / 512 thr = 4 each
        #pragma unroll
        for (int i = 0; i < 4; i++) {
            int idx = tid + i * NT_; int nn = idx >> 4; int c = (idx & 15) * 8;
            int wr = (nn >> 5) * H_ + j0 + (nn & 31);
            cpa16(&sB[nn * LDR_ + c], Ws + (size_t)wr * lw + kk + c);
        }
    };

    float acc[4][4];
    #pragma unroll
    for (int nf = 0; nf < 4; nf++)
        #pragma unroll
        for (int c = 0; c < 4; c++) acc[nf][c] = 0.f;

    stage(0, 0); cpa_commit();
    stage(1, 1); cpa_commit();
    stage(2, 2); cpa_commit();

    for (int kc = 0; kc < nch; kc++) {
        asm volatile("cp.async.wait_group 2;\n" ::: "memory");
        __syncthreads();
        if (kc + 3 < nch) stage(kc + 3, (kc + 3) & 3);
        cpa_commit();

        const unsigned pAu = bufAu[kc & 3];
        const unsigned pBu = bufBu[kc & 3];

        #pragma unroll
        for (int ks = 0; ks < 8; ks++) {
            unsigned a[4];
            {
                int row = wm * 16 + mrow;
                unsigned ad = pAu + (unsigned)(row * LDR_ + mcol + ks * 16) * 2;
                ldsm4(a[0], a[1], a[2], a[3], ad);
            }
            unsigned bb[2][4];
            #pragma unroll
            for (int pq = 0; pq < 2; pq++) {
                int row = wg * 32 + pq * 16 + brow;
                unsigned ad = pBu + (unsigned)(row * LDR_ + bcol + ks * 16) * 2;
                ldsm4(bb[pq][0], bb[pq][1], bb[pq][2], bb[pq][3], ad);
            }
            #pragma unroll
            for (int nf = 0; nf < 4; nf++) {
                unsigned b0 = bb[nf >> 1][(nf & 1) * 2];
                unsigned b1 = bb[nf >> 1][(nf & 1) * 2 + 1];
                asm volatile(
                    "mma.sync.aligned.m16n8k16.row.col.f32.f16.f16.f32 "
                    "{%0,%1,%2,%3}, {%4,%5,%6,%7}, {%8,%9}, {%0,%1,%2,%3};"
                    : "+f"(acc[nf][0]), "+f"(acc[nf][1]),
                      "+f"(acc[nf][2]), "+f"(acc[nf][3])
                    : "r"(a[0]), "r"(a[1]), "r"(a[2]), "r"(a[3]),
                      "r"(b0), "r"(b1));
            }
        }
    }

    asm volatile("cp.async.wait_group 0;\n" ::: "memory");
    __syncthreads();

    // Epilogue: gates -> smem (reuse stage buffers) -> LSTM cell
    float* sG = (float*)sm;   // [gate*64 + m][33], 256*33 floats = 33792 B
    #pragma unroll
    for (int nf = 0; nf < 4; nf++)
        #pragma unroll
        for (int c = 0; c < 4; c++) {
            int row = wm * 16 + grp + ((c & 2) ? 8 : 0);
            int col = nf * 8 + tig * 2 + (c & 1);
            sG[(wg * 64 + row) * 33 + col] = acc[nf][c];
        }
    __syncthreads();

    const float* bs = g_bias[sub];
    const float* done_t = done + (size_t)t * B_;

    #pragma unroll
    for (int i = 0; i < 4; i++) {
        int idx = i * NT_ + tid;
        int m = idx >> 5, j = idx & 31;
        int gm = m0 + m, gj = j0 + j;

        // Hoist latency-bound global loads above the smem gate reads
        size_t off = (size_t)gm * H_ + gj;
        float cp  = c_in[off];
        float msk = 1.0f - done_t[gm];

        float iv = sG[(0 * 64 + m) * 33 + j] + bs[0 * H_ + gj];
        float fv = sG[(1 * 64 + m) * 33 + j] + bs[1 * H_ + gj];
        float gv = sG[(2 * 64 + m) * 33 + j] + bs[2 * H_ + gj];
        float ov = sG[(3 * 64 + m) * 33 + j] + bs[3 * H_ + gj];

        float ii = sigm_(iv);
        float ff = sigm_(fv);
        float gg = tanh_(gv);
        float oo = sigm_(ov);

        float cn = ff * cp + ii * gg;
        float hn = oo * tanh_(cn);

        if (out_raw_f32) out_raw_f32[off] = hn;                  // outputs[t] (pre-mask)
        if (out_raw_h)   out_raw_h[off]   = __float2half_rn(hn); // layer1 input (pre-mask)

        float hm = hn * msk, cm = cn * msk;
        c_out[off]     = cm;
        out_m_f32[off] = hm;
        out_m_h[off]   = __float2half_rn(hm);
    }
}

// ---------------------------------------------------------------------------
// Launch
// ---------------------------------------------------------------------------
extern "C" void kernel_launch(void* const* d_in, const int* in_sizes, int n_in,
                              void* d_out, int out_size) {
    const float* x    = (const float*)d_in[0];
    const float* h0   = (const float*)d_in[1];
    const float* c0   = (const float*)d_in[2];
    const float* done = (const float*)d_in[3];
    const float* Wih0 = (const float*)d_in[4];
    const float* Whh0 = (const float*)d_in[5];
    const float* bih0 = (const float*)d_in[6];
    const float* bhh0 = (const float*)d_in[7];
    const float* Wih1 = (const float*)d_in[8];
    const float* Whh1 = (const float*)d_in[9];
    const float* bih1 = (const float*)d_in[10];
    const float* bhh1 = (const float*)d_in[11];
    float* out = (float*)d_out;

    cudaFuncSetAttribute(lstm_phase, cudaFuncAttributeMaxDynamicSharedMemorySize,
                         SMEM_BYTES);

    prep_kernel<<<592, 256>>>(x, Wih0, Whh0, Wih1, Whh1, bih0, bhh0, bih1, bhh1);
    init_kernel<<<(BH_ + 255) / 256, 256>>>(h0, c0);

    for (int p = 0; p <= S_; p++) {
        lstm_phase<<<128, NT_, SMEM_BYTES>>>(p, done, out);
    }
    final_kernel<<<(BH_ + 255) / 256, 256>>>(out);
}